// round 12
// baseline (speedup 1.0000x reference)
#include <cuda_runtime.h>
#include <cuda_fp16.h>
#include <stdint.h>

#define TPB 256

// ---------------- smem layout (bytes) ----------------
#define T_BUF(b)  ((b) * 8192)          // phase-A gather ping-pong: [64 rows][128B]
#define OFF_BASE  16384                 // fp32 base [64][132] = 33792
#define OFF_SB0   50176
#define OFF_SB1   50688
#define OFF_SB2   51200
#define OFF_SP    51712
#define OFF_SQ    52224
#define OFF_SB3   52736                 // 64 B
#define OFF_LUT   52800                 // 648*4 = 2592
#define OFF_YRED  55392                 // 8 warps * 32 lanes * 8 floats = 8192
#define SMEM_BYTES 65536

// activation pre-scale (keeps branch-3 h1 within fp16 range)
#define ASCL   0.0625f
#define ASCL_I 16.0f

// ---------------- device images ----------------
// Zero-padded input: [8 ch][9 a1][9 a2][34 h][34 w]
__device__ __align__(16) float gInpP[749088];
// fp16 B-fragment packed (uint2 per lane entry):
//   entry = (kblk * nbStride + nblk) * 32 + lane,  lane = (n&7)*4 + ((k>>1)&3)
//   half within entry: ((k>>3)&1)*2 + (k&1)
__device__ __align__(16) __half gW0[90112];  // 704 x 128 (44 kblk x 16 nblk)
__device__ __align__(16) __half gW1[16384];  // 128 x 128 (8 x 16)
__device__ __align__(16) __half gW2[16384];
__device__ __align__(16) __half gW3[2048];   // 128 x 16 (8 x 2)

// ---------------- asm helpers ----------------
__device__ __forceinline__ uint32_t smem_u32(const void* p) {
    uint32_t a;
    asm("{ .reg .u64 t; cvta.to.shared.u64 t, %1; cvt.u32.u64 %0, t; }" : "=r"(a) : "l"(p));
    return a;
}
__device__ __forceinline__ void ldmx4(uint32_t r[4], uint32_t addr) {
    asm volatile("ldmatrix.sync.aligned.m8n8.x4.shared.b16 {%0,%1,%2,%3}, [%4];"
        : "=r"(r[0]), "=r"(r[1]), "=r"(r[2]), "=r"(r[3]) : "r"(addr));
}
__device__ __forceinline__ void mma16816(float* d, const uint32_t* a, uint32_t b0, uint32_t b1) {
    asm volatile("mma.sync.aligned.m16n8k16.row.col.f32.f16.f16.f32 "
        "{%0,%1,%2,%3}, {%4,%5,%6,%7}, {%8,%9}, {%0,%1,%2,%3};"
        : "+f"(d[0]), "+f"(d[1]), "+f"(d[2]), "+f"(d[3])
        : "r"(a[0]), "r"(a[1]), "r"(a[2]), "r"(a[3]), "r"(b0), "r"(b1));
}
__device__ __forceinline__ uint32_t packh2(float v0, float v1) {
    __half2 h = __floats2half2_rn(v0, v1);
    return *(uint32_t*)&h;
}

// ---------------- prep kernel: padded input + fp16 B-frag weights ----------------
__device__ __forceinline__ void pack_frag(__half* dst, float v, int k, int n, int nbStride) {
    int entry = ((k >> 4) * nbStride + (n >> 3)) * 32 + (n & 7) * 4 + ((k >> 1) & 3);
    int sub = ((k >> 3) & 1) * 2 + (k & 1);
    dst[entry * 4 + sub] = __float2half_rn(v);
}

__global__ void prep_kernel(const float* __restrict__ inp,
                            const float* __restrict__ W0, const float* __restrict__ W1,
                            const float* __restrict__ W2, const float* __restrict__ W3) {
    int idx = blockIdx.x * 256 + threadIdx.x;
    const int nP = 749088, n0 = 90112, n1 = 16384, n2 = 16384, n3 = 2048;
    if (idx < nP) {
        int w1 = idx % 34, h1 = (idx / 34) % 34;
        int a2 = (idx / 1156) % 9, a1 = (idx / 10404) % 9, ch = idx / 93636;
        bool ok = (a1 >= 1 && a1 <= 7 && a2 >= 1 && a2 <= 7 &&
                   h1 >= 1 && h1 <= 32 && w1 >= 1 && w1 <= 32);
        gInpP[idx] = ok ? inp[ch * 50176 + (a1 - 1) * 7168 + (a2 - 1) * 1024
                              + (h1 - 1) * 32 + (w1 - 1)] : 0.f;
    } else if (idx < nP + n0) {
        int r = idx - nP, k = r >> 7, n = r & 127;
        float v = (k < 648) ? W0[k * 128 + n] : 0.f;
        pack_frag(gW0, v, k, n, 16);
    } else if (idx < nP + n0 + n1) {
        int r = idx - nP - n0, k = r >> 7, n = r & 127;
        pack_frag(gW1, W1[k * 128 + n], k, n, 16);
    } else if (idx < nP + n0 + n1 + n2) {
        int r = idx - nP - n0 - n1, k = r >> 7, n = r & 127;
        pack_frag(gW2, W2[k * 128 + n], k, n, 16);
    } else if (idx < nP + n0 + n1 + n2 + n3) {
        int r = idx - nP - n0 - n1 - n2, k = r >> 4, n = r & 15;
        float v = (n < 12) ? W3[k * 12 + n] : 0.f;
        pack_frag(gW3, v, k, n, 2);
    }
}

// ---------------- main kernel ----------------
__global__ __launch_bounds__(TPB, 2)
void inr_hmma_kernel(const float* __restrict__ W0,
                     const float* __restrict__ b0g, const float* __restrict__ b1g,
                     const float* __restrict__ b2g, const float* __restrict__ b3g,
                     float* __restrict__ outp) {
    extern __shared__ char sm[];
    const uint32_t sbase = smem_u32(sm);
    const int tid = threadIdx.x;
    const int lane = tid & 31, w = tid >> 5;

    const int blk = blockIdx.x;
    const int ablk = blk >> 4, hgrp = blk & 15;   // 64 positions = 2 h-rows x 32 w
    const int ahi = ablk / 7, awi = ablk % 7;

    float* sBase = (float*)(sm + OFF_BASE);
    float* sb0 = (float*)(sm + OFF_SB0);
    float* sb1 = (float*)(sm + OFF_SB1);
    float* sb2 = (float*)(sm + OFF_SB2);
    float* sP  = (float*)(sm + OFF_SP);
    float* sQ  = (float*)(sm + OFF_SQ);
    float* sb3 = (float*)(sm + OFF_SB3);
    int*   lut = (int*)(sm + OFF_LUT);
    float* yred = (float*)(sm + OFF_YRED);

    for (int c = tid; c < 128; c += TPB) {
        sb0[c] = b0g[c]; sb1[c] = b1g[c]; sb2[c] = b2g[c];
        sP[c] = W0[716 * 128 + c] + W0[717 * 128 + c];
        sQ[c] = W0[718 * 128 + c] + W0[719 * 128 + c];
    }
    if (tid < 12) sb3[tid] = b3g[tid];
    for (int k = tid; k < 648; k += TPB) {
        int aj = k % 3, ai = (k / 3) % 3, kj = (k / 9) % 3, ki = (k / 27) % 3, ch = k / 81;
        lut[k] = ch * 93636 + ai * 10404 + aj * 1156 + ki * 34 + kj;
    }
    __syncthreads();

    const uint2* gw0 = (const uint2*)gW0;
    const uint2* gw1 = (const uint2*)gW1;
    const uint2* gw2 = (const uint2*)gW2;
    const uint2* gw3 = (const uint2*)gW3;

    // fragment coordinates
    const int rq  = lane >> 2;          // 0..7
    const int nqp = (lane & 3) * 2;     // 0,2,4,6

    // ================= Phase A: base = q_feat @ W0 =================
    // 8 warps = 4 m-groups (16 rows) x 2 n-groups (64 cols); K=704, 11 chunks of 64.
    const int mgA = w >> 1, ngA = w & 1;

    float accA[32];
#pragma unroll
    for (int i = 0; i < 32; i++) accA[i] = 0.f;

    const int gm = tid & 63;          // gather: row (position)
    const int gstrip = tid >> 6;      // gather: k-pair strip
    const int ibase = ahi * 10404 + awi * 1156 + hgrp * 68
                    + (gm >> 5) * 34 + (gm & 31);

    auto gather = [&](int c, bool check) {
        char* dh = sm + T_BUF(c & 1);
#pragma unroll
        for (int q = 0; q < 8; q++) {
            int kp = gstrip * 8 + q;
            int kk = c * 64 + kp * 2;
            float v0, v1;
            if (!check) {
                v0 = gInpP[ibase + lut[kk]];
                v1 = gInpP[ibase + lut[kk + 1]];
            } else {
                v0 = (kk < 648) ? gInpP[ibase + lut[kk]] : 0.f;
                v1 = (kk + 1 < 648) ? gInpP[ibase + lut[kk + 1]] : 0.f;
            }
            int off = gm * 128 + ((((kp >> 2) ^ (gm & 7)) << 4)) + (kp & 3) * 4;
            *(uint32_t*)(dh + off) = packh2(v0, v1);
        }
    };

    const int rA = mgA * 16 + (lane & 15);
    const int selA = lane >> 4;
    const int xorA = rA & 7;

    gather(0, false);
    __syncthreads();
    for (int c = 0; c < 11; c++) {
        if (c < 10) gather(c + 1, c + 1 == 10);
        uint32_t aRow = sbase + T_BUF(c & 1) + (rA << 7);
#pragma unroll
        for (int ks = 0; ks < 4; ks++) {
            uint32_t offA = ((uint32_t)(((ks * 2 + selA) ^ xorA))) << 4;
            uint32_t ah[4];
            ldmx4(ah, aRow + offA);
#pragma unroll
            for (int nt = 0; nt < 8; nt++) {
                uint2 bv = gw0[((c * 4 + ks) * 16 + ngA * 8 + nt) * 32 + lane];
                mma16816(accA + nt * 4, ah, bv.x, bv.y);
            }
        }
        __syncthreads();
    }

    // park base in smem fp32 (row stride 132 floats)
#pragma unroll
    for (int nt = 0; nt < 8; nt++) {
        int c = ngA * 64 + nt * 8 + nqp;
        int r0 = mgA * 16 + rq;
        *(float2*)&sBase[r0 * 132 + c]       = make_float2(accA[nt * 4 + 0], accA[nt * 4 + 1]);
        *(float2*)&sBase[(r0 + 8) * 132 + c] = make_float2(accA[nt * 4 + 2], accA[nt * 4 + 3]);
    }
    __syncthreads();

    // ================= branch phase: 2 pairs, all-register chain =================
    // rows = branch_half*64 + pos; warp tile m16 x n128; D->A register repack.
    const int pos16 = (w & 3) * 16;
    const int bh = w >> 2;              // branch half: 0 -> br {0,2}, 1 -> br {1,3}
    const int r0g = pos16 + rq;         // global position of frag row 0
    const float s0 = (hgrp == 0 && r0g < 4) ? (r0g < 2 ? 0.0625f : (2.f / 7.f)) : 1.f;

    float y[8];
#pragma unroll
    for (int i = 0; i < 8; i++) y[i] = 0.f;

    float powv = (bh == 0) ? 32.f : 1024.f;

#pragma unroll 1
    for (int pi = 0; pi < 2; pi++) {
        uint32_t A[32];
        // ---- h1 = relu(base + b0 + s*(powv*P + Q)) * ASCL  (A-frags from smem base) ----
#pragma unroll
        for (int ks = 0; ks < 8; ks++) {
#pragma unroll
            for (int nt2 = 0; nt2 < 2; nt2++) {
                int nt = ks * 2 + nt2;
                int c = nt * 8 + nqp;
                float e0 = fmaf(powv, sP[c], sQ[c]);
                float e1 = fmaf(powv, sP[c + 1], sQ[c + 1]);
                float bb0 = sb0[c], bb1 = sb0[c + 1];
                float2 v0 = *(float2*)&sBase[r0g * 132 + c];
                float2 v1 = *(float2*)&sBase[(r0g + 8) * 132 + c];
                float h00 = fmaxf(v0.x + bb0 + s0 * e0, 0.f) * ASCL;
                float h01 = fmaxf(v0.y + bb1 + s0 * e1, 0.f) * ASCL;
                float h10 = fmaxf(v1.x + bb0 + e0, 0.f) * ASCL;
                float h11 = fmaxf(v1.y + bb1 + e1, 0.f) * ASCL;
                A[ks * 4 + nt2 * 2 + 0] = packh2(h00, h01);
                A[ks * 4 + nt2 * 2 + 1] = packh2(h10, h11);
            }
        }

        // ---- gemm W1 ----
        float acc[64];
#pragma unroll
        for (int i = 0; i < 64; i++) acc[i] = 0.f;
#pragma unroll
        for (int ks = 0; ks < 8; ks++)
#pragma unroll
            for (int nt = 0; nt < 16; nt++) {
                uint2 bv = gw1[(ks * 16 + nt) * 32 + lane];
                mma16816(acc + nt * 4, A + ks * 4, bv.x, bv.y);
            }
        // ---- h2: register D->A repack ----
#pragma unroll
        for (int ks = 0; ks < 8; ks++)
#pragma unroll
            for (int nt2 = 0; nt2 < 2; nt2++) {
                int nt = ks * 2 + nt2;
                int c = nt * 8 + nqp;
                float bb0 = sb1[c], bb1 = sb1[c + 1];
                const float* a = acc + nt * 4;
                A[ks * 4 + nt2 * 2 + 0] = packh2(fmaxf(ASCL_I * a[0] + bb0, 0.f) * ASCL,
                                                 fmaxf(ASCL_I * a[1] + bb1, 0.f) * ASCL);
                A[ks * 4 + nt2 * 2 + 1] = packh2(fmaxf(ASCL_I * a[2] + bb0, 0.f) * ASCL,
                                                 fmaxf(ASCL_I * a[3] + bb1, 0.f) * ASCL);
            }

        // ---- gemm W2 ----
#pragma unroll
        for (int i = 0; i < 64; i++) acc[i] = 0.f;
#pragma unroll
        for (int ks = 0; ks < 8; ks++)
#pragma unroll
            for (int nt = 0; nt < 16; nt++) {
                uint2 bv = gw2[(ks * 16 + nt) * 32 + lane];
                mma16816(acc + nt * 4, A + ks * 4, bv.x, bv.y);
            }
        // ---- h3 repack ----
#pragma unroll
        for (int ks = 0; ks < 8; ks++)
#pragma unroll
            for (int nt2 = 0; nt2 < 2; nt2++) {
                int nt = ks * 2 + nt2;
                int c = nt * 8 + nqp;
                float bb0 = sb2[c], bb1 = sb2[c + 1];
                const float* a = acc + nt * 4;
                A[ks * 4 + nt2 * 2 + 0] = packh2(fmaxf(ASCL_I * a[0] + bb0, 0.f) * ASCL,
                                                 fmaxf(ASCL_I * a[1] + bb1, 0.f) * ASCL);
                A[ks * 4 + nt2 * 2 + 1] = packh2(fmaxf(ASCL_I * a[2] + bb0, 0.f) * ASCL,
                                                 fmaxf(ASCL_I * a[3] + bb1, 0.f) * ASCL);
            }

        // ---- gemm W3 (n=16) -> y accumulate ----
#pragma unroll
        for (int ks = 0; ks < 8; ks++)
#pragma unroll
            for (int nt = 0; nt < 2; nt++) {
                uint2 bv = gw3[(ks * 2 + nt) * 32 + lane];
                mma16816(y + nt * 4, A + ks * 4, bv.x, bv.y);
            }

        powv *= 1024.f;   // 32^2 per pair step
    }

    // ---- reduce branch halves: warps 4-7 park y, warps 0-3 combine + scatter ----
    if (w >= 4) {
#pragma unroll
        for (int i = 0; i < 8; i++) yred[((w - 4) * 32 + lane) * 8 + i] = y[i];
    }
    __syncthreads();
    if (w < 4) {
#pragma unroll
        for (int nt = 0; nt < 2; nt++)
#pragma unroll
            for (int half = 0; half < 2; half++)
#pragma unroll
                for (int j = 0; j < 2; j++) {
                    int n = nt * 8 + nqp + j;
                    if (n < 12) {
                        int idx = nt * 4 + half * 2 + j;
                        float yo = yred[(w * 32 + lane) * 8 + idx];
                        float val = 4.0f * (y[idx] + yo) + sb3[n];
                        int r = pos16 + rq + half * 8;
                        int hi = hgrp * 2 + (r >> 5), wi = r & 31;
                        int rgb = n >> 2, pr = (n >> 1) & 1, qc = n & 1;
                        outp[rgb * 200704 + ahi * 28672 + awi * 4096 +
                             (2 * hi + pr) * 64 + (2 * wi + qc)] = val;
                    }
                }
    }
}

extern "C" void kernel_launch(void* const* d_in, const int* in_sizes, int n_in,
                              void* d_out, int out_size) {
    (void)in_sizes; (void)n_in; (void)out_size;
    const float* inp = (const float*)d_in[0];
    const float* W0  = (const float*)d_in[1];
    const float* b0  = (const float*)d_in[2];
    const float* W1  = (const float*)d_in[3];
    const float* b1  = (const float*)d_in[4];
    const float* W2  = (const float*)d_in[5];
    const float* b2  = (const float*)d_in[6];
    const float* W3  = (const float*)d_in[7];
    const float* b3  = (const float*)d_in[8];
    float* outp = (float*)d_out;

    const int prep_tasks = 749088 + 90112 + 16384 + 16384 + 2048;
    prep_kernel<<<(prep_tasks + 255) / 256, 256>>>(inp, W0, W1, W2, W3);

    cudaFuncSetAttribute(inr_hmma_kernel, cudaFuncAttributeMaxDynamicSharedMemorySize, SMEM_BYTES);
    inr_hmma_kernel<<<784, TPB, SMEM_BYTES>>>(W0, b0, b1, b2, b3, outp);
}

// round 13
// speedup vs baseline: 1.1264x; 1.1264x over previous
#include <cuda_runtime.h>
#include <cuda_fp16.h>
#include <stdint.h>

#define TPB 256

// ---------------- smem layout (bytes) ----------------
#define OFF_EXCH  0                    // 2 x 16 KB exchange buffers (double-buffered)
#define T_BUF(b)  ((b) * 8192)         // phase-A gather ping-pong aliases exchange region
#define OFF_BASE  32768                // fp32 base [64][132] = 33792
#define OFF_SB0   66560
#define OFF_SB1   67072
#define OFF_SB2   67584
#define OFF_SP    68096
#define OFF_SQ    68608
#define OFF_SB3   69120                // 64 B
#define OFF_LUT   69184                // 648*4 = 2592
#define SMEM_BYTES 73728

// activation pre-scale (keeps branch-3 h1 within fp16 range)
#define ASCL   0.0625f
#define ASCL_I 16.0f

// ---------------- device images ----------------
// Zero-padded input: [8 ch][9 a1][9 a2][34 h][34 w]
__device__ __align__(16) float gInpP[749088];
// fp16 B-fragment packed (uint2 per lane entry):
//   entry = (kblk * nbStride + nblk) * 32 + lane,  lane = (n&7)*4 + ((k>>1)&3)
//   half within entry: ((k>>3)&1)*2 + (k&1)
__device__ __align__(16) __half gW0[90112];  // 704 x 128 (44 kblk x 16 nblk)
__device__ __align__(16) __half gW1[16384];  // 128 x 128 (8 x 16)
__device__ __align__(16) __half gW2[16384];
__device__ __align__(16) __half gW3[2048];   // 128 x 16 (8 x 2)

// ---------------- asm helpers ----------------
__device__ __forceinline__ uint32_t smem_u32(const void* p) {
    uint32_t a;
    asm("{ .reg .u64 t; cvta.to.shared.u64 t, %1; cvt.u32.u64 %0, t; }" : "=r"(a) : "l"(p));
    return a;
}
__device__ __forceinline__ void ldmx4(uint32_t r[4], uint32_t addr) {
    asm volatile("ldmatrix.sync.aligned.m8n8.x4.shared.b16 {%0,%1,%2,%3}, [%4];"
        : "=r"(r[0]), "=r"(r[1]), "=r"(r[2]), "=r"(r[3]) : "r"(addr));
}
__device__ __forceinline__ void mma16816(float* d, const uint32_t* a, uint32_t b0, uint32_t b1) {
    asm volatile("mma.sync.aligned.m16n8k16.row.col.f32.f16.f16.f32 "
        "{%0,%1,%2,%3}, {%4,%5,%6,%7}, {%8,%9}, {%0,%1,%2,%3};"
        : "+f"(d[0]), "+f"(d[1]), "+f"(d[2]), "+f"(d[3])
        : "r"(a[0]), "r"(a[1]), "r"(a[2]), "r"(a[3]), "r"(b0), "r"(b1));
}
__device__ __forceinline__ uint32_t packh2(float v0, float v1) {
    __half2 h = __floats2half2_rn(v0, v1);
    return *(uint32_t*)&h;
}

// ---------------- prep kernel: padded input + fp16 B-frag weights ----------------
__device__ __forceinline__ void pack_frag(__half* dst, float v, int k, int n, int nbStride) {
    int entry = ((k >> 4) * nbStride + (n >> 3)) * 32 + (n & 7) * 4 + ((k >> 1) & 3);
    int sub = ((k >> 3) & 1) * 2 + (k & 1);
    dst[entry * 4 + sub] = __float2half_rn(v);
}

__global__ void prep_kernel(const float* __restrict__ inp,
                            const float* __restrict__ W0, const float* __restrict__ W1,
                            const float* __restrict__ W2, const float* __restrict__ W3) {
    int idx = blockIdx.x * 256 + threadIdx.x;
    const int nP = 749088, n0 = 90112, n1 = 16384, n2 = 16384, n3 = 2048;
    if (idx < nP) {
        int w1 = idx % 34, h1 = (idx / 34) % 34;
        int a2 = (idx / 1156) % 9, a1 = (idx / 10404) % 9, ch = idx / 93636;
        bool ok = (a1 >= 1 && a1 <= 7 && a2 >= 1 && a2 <= 7 &&
                   h1 >= 1 && h1 <= 32 && w1 >= 1 && w1 <= 32);
        gInpP[idx] = ok ? inp[ch * 50176 + (a1 - 1) * 7168 + (a2 - 1) * 1024
                              + (h1 - 1) * 32 + (w1 - 1)] : 0.f;
    } else if (idx < nP + n0) {
        int r = idx - nP, k = r >> 7, n = r & 127;
        float v = (k < 648) ? W0[k * 128 + n] : 0.f;
        pack_frag(gW0, v, k, n, 16);
    } else if (idx < nP + n0 + n1) {
        int r = idx - nP - n0, k = r >> 7, n = r & 127;
        pack_frag(gW1, W1[k * 128 + n], k, n, 16);
    } else if (idx < nP + n0 + n1 + n2) {
        int r = idx - nP - n0 - n1, k = r >> 7, n = r & 127;
        pack_frag(gW2, W2[k * 128 + n], k, n, 16);
    } else if (idx < nP + n0 + n1 + n2 + n3) {
        int r = idx - nP - n0 - n1 - n2, k = r >> 4, n = r & 15;
        float v = (n < 12) ? W3[k * 12 + n] : 0.f;
        pack_frag(gW3, v, k, n, 2);
    }
}

// ---------------- main kernel ----------------
__global__ __launch_bounds__(TPB, 2)
void inr_hmma_kernel(const float* __restrict__ W0,
                     const float* __restrict__ b0g, const float* __restrict__ b1g,
                     const float* __restrict__ b2g, const float* __restrict__ b3g,
                     float* __restrict__ outp) {
    extern __shared__ char sm[];
    const uint32_t sbase = smem_u32(sm);
    const int tid = threadIdx.x;
    const int lane = tid & 31, w = tid >> 5;

    const int blk = blockIdx.x;
    const int ablk = blk >> 4, hgrp = blk & 15;   // 64 positions = 2 h-rows x 32 w
    const int ahi = ablk / 7, awi = ablk % 7;

    float* sBase = (float*)(sm + OFF_BASE);
    float* sb0 = (float*)(sm + OFF_SB0);
    float* sb1 = (float*)(sm + OFF_SB1);
    float* sb2 = (float*)(sm + OFF_SB2);
    float* sP  = (float*)(sm + OFF_SP);
    float* sQ  = (float*)(sm + OFF_SQ);
    float* sb3 = (float*)(sm + OFF_SB3);
    int*   lut = (int*)(sm + OFF_LUT);

    for (int c = tid; c < 128; c += TPB) {
        sb0[c] = b0g[c]; sb1[c] = b1g[c]; sb2[c] = b2g[c];
        sP[c] = W0[716 * 128 + c] + W0[717 * 128 + c];
        sQ[c] = W0[718 * 128 + c] + W0[719 * 128 + c];
    }
    if (tid < 12) sb3[tid] = b3g[tid];
    for (int k = tid; k < 648; k += TPB) {
        int aj = k % 3, ai = (k / 3) % 3, kj = (k / 9) % 3, ki = (k / 27) % 3, ch = k / 81;
        lut[k] = ch * 93636 + ai * 10404 + aj * 1156 + ki * 34 + kj;
    }
    __syncthreads();

    const uint2* gw0 = (const uint2*)gW0;
    const uint2* gw1 = (const uint2*)gW1;
    const uint2* gw2 = (const uint2*)gW2;
    const uint2* gw3 = (const uint2*)gW3;

    // fragment coordinates
    const int rq  = lane >> 2;          // 0..7
    const int nqp = (lane & 3) * 2;     // 0,2,4,6
    // warp tiling (both phases): 4 m-groups (16 rows) x 2 n-groups
    const int mg = w >> 1, ng = w & 1;

    // ================= Phase A: base = q_feat @ W0 =================
    float accA[32];
#pragma unroll
    for (int i = 0; i < 32; i++) accA[i] = 0.f;

    const int gm = tid & 63;          // gather: row (position)
    const int gstrip = tid >> 6;      // gather: k-pair strip
    const int ibase = ahi * 10404 + awi * 1156 + hgrp * 68
                    + (gm >> 5) * 34 + (gm & 31);

    auto gather = [&](int c, bool check) {
        char* dh = sm + T_BUF(c & 1);
#pragma unroll
        for (int q = 0; q < 8; q++) {
            int kp = gstrip * 8 + q;
            int kk = c * 64 + kp * 2;
            float v0, v1;
            if (!check) {
                v0 = gInpP[ibase + lut[kk]];
                v1 = gInpP[ibase + lut[kk + 1]];
            } else {
                v0 = (kk < 648) ? gInpP[ibase + lut[kk]] : 0.f;
                v1 = (kk + 1 < 648) ? gInpP[ibase + lut[kk + 1]] : 0.f;
            }
            int off = gm * 128 + ((((kp >> 2) ^ (gm & 7)) << 4)) + (kp & 3) * 4;
            *(uint32_t*)(dh + off) = packh2(v0, v1);
        }
    };

    const int rA = mg * 16 + (lane & 15);
    const int selA = lane >> 4;
    const int xorA = rA & 7;

    gather(0, false);
    __syncthreads();
    for (int c = 0; c < 11; c++) {
        if (c < 10) gather(c + 1, c + 1 == 10);
        uint32_t aRow = sbase + T_BUF(c & 1) + (rA << 7);
#pragma unroll
        for (int ks = 0; ks < 4; ks++) {
            uint32_t offA = ((uint32_t)(((ks * 2 + selA) ^ xorA))) << 4;
            uint32_t ah[4];
            ldmx4(ah, aRow + offA);
#pragma unroll
            for (int nt = 0; nt < 8; nt++) {
                uint2 bv = gw0[((c * 4 + ks) * 16 + ng * 8 + nt) * 32 + lane];
                mma16816(accA + nt * 4, ah, bv.x, bv.y);
            }
        }
        __syncthreads();
    }

    // park base in smem fp32 (row stride 132 floats)
#pragma unroll
    for (int nt = 0; nt < 8; nt++) {
        int c = ng * 64 + nt * 8 + nqp;
        int r0 = mg * 16 + rq;
        *(float2*)&sBase[r0 * 132 + c]       = make_float2(accA[nt * 4 + 0], accA[nt * 4 + 1]);
        *(float2*)&sBase[(r0 + 8) * 132 + c] = make_float2(accA[nt * 4 + 2], accA[nt * 4 + 3]);
    }
    __syncthreads();

    // ================= 4 branches: all-register chain + half-exchange =================
    const int r0g = mg * 16 + rq;
    const float s0 = (hgrp == 0 && r0g < 4) ? (r0g < 2 ? 0.0625f : (2.f / 7.f)) : 1.f;

    // exchange addresses (own slot / partner slot), double-buffered
    const uint32_t exOwn  = sbase + OFF_EXCH + w * 2048 + lane * 64;
    const uint32_t exPeer = sbase + OFF_EXCH + (w ^ 1) * 2048 + lane * 64;

    float y[4] = {0.f, 0.f, 0.f, 0.f};
    float powv = 32.f;

#pragma unroll 1
    for (int br = 0; br < 4; br++) {
        uint32_t A[32];
        // ---- h1 = relu(base + b0 + s*(powv*P + Q)) * ASCL  (full K=128 from sBase) ----
#pragma unroll
        for (int ks = 0; ks < 8; ks++) {
#pragma unroll
            for (int nt2 = 0; nt2 < 2; nt2++) {
                int c = ks * 16 + nt2 * 8 + nqp;
                float e0 = fmaf(powv, sP[c], sQ[c]);
                float e1 = fmaf(powv, sP[c + 1], sQ[c + 1]);
                float bb0 = sb0[c], bb1 = sb0[c + 1];
                float2 v0 = *(float2*)&sBase[r0g * 132 + c];
                float2 v1 = *(float2*)&sBase[(r0g + 8) * 132 + c];
                A[ks * 4 + nt2 * 2 + 0] = packh2(fmaxf(v0.x + bb0 + s0 * e0, 0.f) * ASCL,
                                                 fmaxf(v0.y + bb1 + s0 * e1, 0.f) * ASCL);
                A[ks * 4 + nt2 * 2 + 1] = packh2(fmaxf(v1.x + bb0 + e0, 0.f) * ASCL,
                                                 fmaxf(v1.y + bb1 + e1, 0.f) * ASCL);
            }
        }

        // ---- two hidden layers: gemm(n=64 own half) -> repack own -> exchange ----
#pragma unroll
        for (int layer = 0; layer < 2; layer++) {
            const uint2* gw = (layer == 0) ? gw1 : gw2;
            const float* bias = (layer == 0) ? sb1 : sb2;

            float acc[32];
#pragma unroll
            for (int i = 0; i < 32; i++) acc[i] = 0.f;
#pragma unroll
            for (int ks = 0; ks < 8; ks++)
#pragma unroll
                for (int nt = 0; nt < 8; nt++) {
                    uint2 bv = gw[(ks * 16 + ng * 8 + nt) * 32 + lane];
                    mma16816(acc + nt * 4, A + ks * 4, bv.x, bv.y);
                }

            // repack own n-half into A[ng*16 .. ng*16+15]
#pragma unroll
            for (int nt = 0; nt < 8; nt++) {
                int c = ng * 64 + nt * 8 + nqp;
                float bb0 = bias[c], bb1 = bias[c + 1];
                const float* a = acc + nt * 4;
                int dst = ng * 16 + (nt >> 1) * 4 + (nt & 1) * 2;
                A[dst + 0] = packh2(fmaxf(ASCL_I * a[0] + bb0, 0.f) * ASCL,
                                    fmaxf(ASCL_I * a[1] + bb1, 0.f) * ASCL);
                A[dst + 1] = packh2(fmaxf(ASCL_I * a[2] + bb0, 0.f) * ASCL,
                                    fmaxf(ASCL_I * a[3] + bb1, 0.f) * ASCL);
            }

            // exchange other half with partner warp (double-buffered slot)
            uint32_t ebuf = (uint32_t)(((br * 2 + layer) & 1) * 16384);
#pragma unroll
            for (int i = 0; i < 4; i++) {
                uint4 v = make_uint4(A[ng * 16 + i * 4 + 0], A[ng * 16 + i * 4 + 1],
                                     A[ng * 16 + i * 4 + 2], A[ng * 16 + i * 4 + 3]);
                asm volatile("st.shared.v4.b32 [%0], {%1,%2,%3,%4};"
                    :: "r"(exOwn + ebuf + i * 16), "r"(v.x), "r"(v.y), "r"(v.z), "r"(v.w)
                    : "memory");
            }
            __syncthreads();
#pragma unroll
            for (int i = 0; i < 4; i++) {
                uint4 v;
                asm volatile("ld.shared.v4.b32 {%0,%1,%2,%3}, [%4];"
                    : "=r"(v.x), "=r"(v.y), "=r"(v.z), "=r"(v.w)
                    : "r"(exPeer + ebuf + i * 16));
                int dst = (ng ^ 1) * 16 + i * 4;
                A[dst + 0] = v.x; A[dst + 1] = v.y; A[dst + 2] = v.z; A[dst + 3] = v.w;
            }
        }

        // ---- W3 (n=16): warp computes own n-block ng (cols ng*8..ng*8+7) ----
#pragma unroll
        for (int ks = 0; ks < 8; ks++) {
            uint2 bv = gw3[(ks * 2 + ng) * 32 + lane];
            mma16816(y, A + ks * 4, bv.x, bv.y);
        }
        powv *= 32.f;
    }

    // ---- scatter (pixel shuffle); y_true = 16*y, out = 0.25*sum + b3 = 4*y + b3 ----
#pragma unroll
    for (int half = 0; half < 2; half++)
#pragma unroll
        for (int j = 0; j < 2; j++) {
            int n = ng * 8 + nqp + j;
            if (n < 12) {
                float val = 4.0f * y[half * 2 + j] + sb3[n];
                int r = r0g + half * 8;
                int hi = hgrp * 2 + (r >> 5), wi = r & 31;
                int rgb = n >> 2, pr = (n >> 1) & 1, qc = n & 1;
                outp[rgb * 200704 + ahi * 28672 + awi * 4096 +
                     (2 * hi + pr) * 64 + (2 * wi + qc)] = val;
            }
        }
}

extern "C" void kernel_launch(void* const* d_in, const int* in_sizes, int n_in,
                              void* d_out, int out_size) {
    (void)in_sizes; (void)n_in; (void)out_size;
    const float* inp = (const float*)d_in[0];
    const float* W0  = (const float*)d_in[1];
    const float* b0  = (const float*)d_in[2];
    const float* W1  = (const float*)d_in[3];
    const float* b1  = (const float*)d_in[4];
    const float* W2  = (const float*)d_in[5];
    const float* b2  = (const float*)d_in[6];
    const float* W3  = (const float*)d_in[7];
    const float* b3  = (const float*)d_in[8];
    float* outp = (float*)d_out;

    const int prep_tasks = 749088 + 90112 + 16384 + 16384 + 2048;
    prep_kernel<<<(prep_tasks + 255) / 256, 256>>>(inp, W0, W1, W2, W3);

    cudaFuncSetAttribute(inr_hmma_kernel, cudaFuncAttributeMaxDynamicSharedMemorySize, SMEM_BYTES);
    inr_hmma_kernel<<<784, TPB, SMEM_BYTES>>>(W0, b0, b1, b2, b3, outp);
}

// round 14
// speedup vs baseline: 1.6122x; 1.4313x over previous
#include <cuda_runtime.h>
#include <cuda_fp16.h>
#include <stdint.h>

#define TPB 128

// ---------------- smem layout (bytes) ----------------
// Branch-phase double-buffered A tiles (hi only): [32 rows][256B] = 8 KB each
#define T_BUF(b)   ((b) * 8192)
// Phase-A chunk buffers alias the same region: [32 rows][128B] = 4 KB each
#define PA_BUF(b)  ((b) * 4096)
#define OFF_SB0   16384
#define OFF_SB1   16896
#define OFF_SB2   17408
#define OFF_SP    17920
#define OFF_SQ    18432
#define OFF_SB3   18944    // 64 B
#define OFF_LUT   19008    // 648*4 = 2592
#define SMEM_BYTES 22528

// activation pre-scale (keeps branch-3 h1 within fp16 range)
#define ASCL   0.0625f
#define ASCL_I 16.0f

// ---------------- device images ----------------
// Zero-padded input: [8 ch][9 a1][9 a2][34 h][34 w]
__device__ __align__(16) float gInpP[749088];
// fp16 B-fragment packed (uint2 per lane entry):
//   entry = (kblk * nbStride + nblk) * 32 + lane,  lane = (n&7)*4 + ((k>>1)&3)
//   half within entry: ((k>>3)&1)*2 + (k&1)
__device__ __align__(16) __half gW0[90112];  // 704 x 128 (44 kblk x 16 nblk)
__device__ __align__(16) __half gW1[16384];  // 128 x 128 (8 x 16)
__device__ __align__(16) __half gW2[16384];
__device__ __align__(16) __half gW3[2048];   // 128 x 16 (8 x 2)

// ---------------- asm helpers ----------------
__device__ __forceinline__ uint32_t smem_u32(const void* p) {
    uint32_t a;
    asm("{ .reg .u64 t; cvta.to.shared.u64 t, %1; cvt.u32.u64 %0, t; }" : "=r"(a) : "l"(p));
    return a;
}
__device__ __forceinline__ void ldmx4(uint32_t r[4], uint32_t addr) {
    asm volatile("ldmatrix.sync.aligned.m8n8.x4.shared.b16 {%0,%1,%2,%3}, [%4];"
        : "=r"(r[0]), "=r"(r[1]), "=r"(r[2]), "=r"(r[3]) : "r"(addr));
}
__device__ __forceinline__ void mma16816(float* d, const uint32_t* a, uint32_t b0, uint32_t b1) {
    asm volatile("mma.sync.aligned.m16n8k16.row.col.f32.f16.f16.f32 "
        "{%0,%1,%2,%3}, {%4,%5,%6,%7}, {%8,%9}, {%0,%1,%2,%3};"
        : "+f"(d[0]), "+f"(d[1]), "+f"(d[2]), "+f"(d[3])
        : "r"(a[0]), "r"(a[1]), "r"(a[2]), "r"(a[3]), "r"(b0), "r"(b1));
}
__device__ __forceinline__ uint32_t packh2(float v0, float v1) {
    __half2 h = __floats2half2_rn(v0, v1);
    return *(uint32_t*)&h;
}

// GEMM: A (fp16, 1-term) from swizzled smem via ldmatrix, B uint2 frags from global.
// Warp computes rows [0, 16*MT) x cols [nblk0*8, (nblk0+NT)*8).
template<int KS, int MT, int NT, int RLOG>
__device__ __forceinline__ void gemm_gb(uint32_t aBuf,
    const uint2* __restrict__ gB,
    int kblk0, int nbStride, int nblk0, float* acc, int lane)
{
    const int rA = lane & 15;
    const int selA = lane >> 4;
    const uint32_t aRow = aBuf + (rA << RLOG);
    const int xorA = rA & 7;
    const uint2* b = gB + (kblk0 * nbStride + nblk0) * 32 + lane;
#pragma unroll
    for (int ks = 0; ks < KS; ks++) {
        const uint32_t offA = ((uint32_t)(((ks * 2 + selA) ^ xorA))) << 4;
        uint32_t ah[MT][4];
#pragma unroll
        for (int mt = 0; mt < MT; mt++)
            ldmx4(ah[mt], aRow + (mt << (RLOG + 4)) + offA);
        uint2 bv[NT];
#pragma unroll
        for (int nt = 0; nt < NT; nt++) bv[nt] = b[nt * 32];
        b += nbStride * 32;
#pragma unroll
        for (int nt = 0; nt < NT; nt++)
#pragma unroll
            for (int mt = 0; mt < MT; mt++)
                mma16816(acc + (mt * NT + nt) * 4, ah[mt], bv[nt].x, bv[nt].y);
    }
}

// epilogue: D frags (ASCL_I*acc + bias [+cell term]) -> relu -> fp16 (xASCL) -> smem hi tile
template<bool EXTRA, bool RESCALE>
__device__ __forceinline__ void epi(char* sm, uint32_t dstOff, const float* acc, const float* bias,
                                    float powv, const float* sP, const float* sQ,
                                    int ng, int lane, int hgrp)
{
    const int rq = lane >> 2, nq = (lane & 3) * 2;
#pragma unroll
    for (int mt = 0; mt < 2; mt++) {
#pragma unroll
        for (int nt = 0; nt < 4; nt++) {
            int n = ng * 32 + nt * 8 + nq;
            float bb0 = bias[n], bb1 = bias[n + 1];
            float e0 = 0.f, e1 = 0.f;
            if (EXTRA) { e0 = fmaf(powv, sP[n], sQ[n]); e1 = fmaf(powv, sP[n + 1], sQ[n + 1]); }
            const float* a = acc + (mt * 4 + nt) * 4;
#pragma unroll
            for (int half = 0; half < 2; half++) {
                int r = mt * 16 + rq + half * 8;
                float av0 = RESCALE ? ASCL_I * a[half * 2 + 0] : a[half * 2 + 0];
                float av1 = RESCALE ? ASCL_I * a[half * 2 + 1] : a[half * 2 + 1];
                float v0 = av0 + bb0;
                float v1 = av1 + bb1;
                if (EXTRA) {
                    float s = 1.f;
                    if (hgrp == 0 && r < 4) s = (r < 2) ? 0.0625f : (2.f / 7.f);
                    v0 += s * e0; v1 += s * e1;
                }
                v0 = fmaxf(v0, 0.f) * ASCL;
                v1 = fmaxf(v1, 0.f) * ASCL;
                int off = (r << 8) + ((((n >> 3) ^ (r & 7)) << 4)) + (n & 7) * 2;
                *(uint32_t*)(sm + dstOff + off) = packh2(v0, v1);
            }
        }
    }
}

// ---------------- prep kernel: padded input + fp16 B-frag weights ----------------
__device__ __forceinline__ void pack_frag(__half* dst, float v, int k, int n, int nbStride) {
    int entry = ((k >> 4) * nbStride + (n >> 3)) * 32 + (n & 7) * 4 + ((k >> 1) & 3);
    int sub = ((k >> 3) & 1) * 2 + (k & 1);
    dst[entry * 4 + sub] = __float2half_rn(v);
}

__global__ void prep_kernel(const float* __restrict__ inp,
                            const float* __restrict__ W0, const float* __restrict__ W1,
                            const float* __restrict__ W2, const float* __restrict__ W3) {
    int idx = blockIdx.x * 256 + threadIdx.x;
    const int nP = 749088, n0 = 90112, n1 = 16384, n2 = 16384, n3 = 2048;
    if (idx < nP) {
        int w1 = idx % 34, h1 = (idx / 34) % 34;
        int a2 = (idx / 1156) % 9, a1 = (idx / 10404) % 9, ch = idx / 93636;
        bool ok = (a1 >= 1 && a1 <= 7 && a2 >= 1 && a2 <= 7 &&
                   h1 >= 1 && h1 <= 32 && w1 >= 1 && w1 <= 32);
        gInpP[idx] = ok ? inp[ch * 50176 + (a1 - 1) * 7168 + (a2 - 1) * 1024
                              + (h1 - 1) * 32 + (w1 - 1)] : 0.f;
    } else if (idx < nP + n0) {
        int r = idx - nP, k = r >> 7, n = r & 127;
        float v = (k < 648) ? W0[k * 128 + n] : 0.f;
        pack_frag(gW0, v, k, n, 16);
    } else if (idx < nP + n0 + n1) {
        int r = idx - nP - n0, k = r >> 7, n = r & 127;
        pack_frag(gW1, W1[k * 128 + n], k, n, 16);
    } else if (idx < nP + n0 + n1 + n2) {
        int r = idx - nP - n0 - n1, k = r >> 7, n = r & 127;
        pack_frag(gW2, W2[k * 128 + n], k, n, 16);
    } else if (idx < nP + n0 + n1 + n2 + n3) {
        int r = idx - nP - n0 - n1 - n2, k = r >> 4, n = r & 15;
        float v = (n < 12) ? W3[k * 12 + n] : 0.f;
        pack_frag(gW3, v, k, n, 2);
    }
}

// ---------------- main kernel ----------------
__global__ __launch_bounds__(TPB, 4)
void inr_hmma_kernel(const float* __restrict__ W0,
                     const float* __restrict__ b0g, const float* __restrict__ b1g,
                     const float* __restrict__ b2g, const float* __restrict__ b3g,
                     float* __restrict__ outp) {
    extern __shared__ char sm[];
    const uint32_t sbase = smem_u32(sm);
    const int tid = threadIdx.x;
    const int lane = tid & 31, w = tid >> 5;
    const int ng = w;                          // 4 warps: 1 m-group (32 rows) x 4 n-groups

    const int blk = blockIdx.x;
    const int ablk = blk >> 5, hgrp = blk & 31;   // 32 positions = 1 h-row x 32 w
    const int ahi = ablk / 7, awi = ablk % 7;

    float* sb0 = (float*)(sm + OFF_SB0);
    float* sb1 = (float*)(sm + OFF_SB1);
    float* sb2 = (float*)(sm + OFF_SB2);
    float* sP  = (float*)(sm + OFF_SP);
    float* sQ  = (float*)(sm + OFF_SQ);
    float* sb3 = (float*)(sm + OFF_SB3);
    int*   lut = (int*)(sm + OFF_LUT);

    for (int c = tid; c < 128; c += TPB) {
        sb0[c] = b0g[c]; sb1[c] = b1g[c]; sb2[c] = b2g[c];
        sP[c] = W0[716 * 128 + c] + W0[717 * 128 + c];
        sQ[c] = W0[718 * 128 + c] + W0[719 * 128 + c];
    }
    if (tid < 12) sb3[tid] = b3g[tid];
    for (int k = tid; k < 648; k += TPB) {
        int aj = k % 3, ai = (k / 3) % 3, kj = (k / 9) % 3, ki = (k / 27) % 3, ch = k / 81;
        lut[k] = ch * 93636 + ai * 10404 + aj * 1156 + ki * 34 + kj;
    }
    __syncthreads();

    const uint2* gw0 = (const uint2*)gW0;
    const uint2* gw1 = (const uint2*)gW1;
    const uint2* gw2 = (const uint2*)gW2;
    const uint2* gw3 = (const uint2*)gW3;

    // ================= Phase A: base = q_feat @ W0 (11 chunks of K=64, ping-pong) ======
    float base_[32];
#pragma unroll
    for (int i = 0; i < 32; i++) base_[i] = 0.f;

    const int gm = tid & 31;          // row (position = w-index)
    const int gstrip = tid >> 5;      // k-pair strip (0..3)
    const int ibase = ahi * 10404 + awi * 1156 + hgrp * 34 + gm;

    auto gather = [&](int c, bool check) {
        char* dh = sm + PA_BUF(c & 1);
#pragma unroll
        for (int q = 0; q < 8; q++) {
            int kp = gstrip * 8 + q;
            int kk = c * 64 + kp * 2;
            float v0, v1;
            if (!check) {
                v0 = gInpP[ibase + lut[kk]];
                v1 = gInpP[ibase + lut[kk + 1]];
            } else {
                v0 = (kk < 648) ? gInpP[ibase + lut[kk]] : 0.f;
                v1 = (kk + 1 < 648) ? gInpP[ibase + lut[kk + 1]] : 0.f;
            }
            int off = gm * 128 + ((((kp >> 2) ^ (gm & 7)) << 4)) + (kp & 3) * 4;
            *(uint32_t*)(dh + off) = packh2(v0, v1);
        }
    };

    gather(0, false);
    __syncthreads();
    for (int c = 0; c < 11; c++) {
        if (c < 10) gather(c + 1, c + 1 == 10);
        gemm_gb<4, 2, 4, 7>(sbase + PA_BUF(c & 1), gw0,
                            c * 4, 16, ng * 4, base_, lane);
        __syncthreads();
    }

    // ================= 4 branches (ping-pong hi-only activation tiles) =================
    float y[8];
#pragma unroll
    for (int i = 0; i < 8; i++) y[i] = 0.f;
    float powv = 32.f;
    int p = 0;

    for (int br = 0; br < 4; br++) {
        // h1 = relu(base + b0 + s*(powv*P + Q)) -> buf p   (base unscaled: RESCALE=false)
        epi<true, false>(sm, T_BUF(p), base_, sb0, powv, sP, sQ, ng, lane, hgrp);
        __syncthreads();

        float acc[32];
#pragma unroll
        for (int i = 0; i < 32; i++) acc[i] = 0.f;
        gemm_gb<8, 2, 4, 8>(sbase + T_BUF(p), gw1, 0, 16, ng * 4, acc, lane);
        // h2 -> buf p^1 (writes other buffer; no pre-sync needed)
        epi<false, true>(sm, T_BUF(p ^ 1), acc, sb1, 0.f, sP, sQ, ng, lane, hgrp);
        __syncthreads();

#pragma unroll
        for (int i = 0; i < 32; i++) acc[i] = 0.f;
        gemm_gb<8, 2, 4, 8>(sbase + T_BUF(p ^ 1), gw2, 0, 16, ng * 4, acc, lane);
        // h3 -> buf p
        epi<false, true>(sm, T_BUF(p), acc, sb2, 0.f, sP, sQ, ng, lane, hgrp);
        __syncthreads();

        // y += (h3/16) @ W3 (warps with ng<2; nblk = ng selects 8-col block of N=16)
        if (ng < 2) {
            gemm_gb<8, 2, 1, 8>(sbase + T_BUF(p), gw3, 0, 2, ng, y, lane);
        }
        p ^= 1;
        powv *= 32.f;
    }

    // ---- scatter (pixel shuffle); y_true = 16*y, out = 0.25*sum + b3 = 4*y + b3 ----
    if (ng < 2) {
        const int rq = lane >> 2, nq = (lane & 3) * 2;
#pragma unroll
        for (int mt = 0; mt < 2; mt++)
#pragma unroll
            for (int half = 0; half < 2; half++)
#pragma unroll
                for (int j = 0; j < 2; j++) {
                    int n = ng * 8 + nq + j;
                    if (n < 12) {
                        int r = mt * 16 + rq + half * 8;   // position (w-index) 0..31
                        float val = 4.0f * y[mt * 4 + half * 2 + j] + sb3[n];
                        int hi = hgrp, wi = r;
                        int rgb = n >> 2, pr = (n >> 1) & 1, qc = n & 1;
                        outp[rgb * 200704 + ahi * 28672 + awi * 4096 +
                             (2 * hi + pr) * 64 + (2 * wi + qc)] = val;
                    }
                }
    }
}

extern "C" void kernel_launch(void* const* d_in, const int* in_sizes, int n_in,
                              void* d_out, int out_size) {
    (void)in_sizes; (void)n_in; (void)out_size;
    const float* inp = (const float*)d_in[0];
    const float* W0  = (const float*)d_in[1];
    const float* b0  = (const float*)d_in[2];
    const float* W1  = (const float*)d_in[3];
    const float* b1  = (const float*)d_in[4];
    const float* W2  = (const float*)d_in[5];
    const float* b2  = (const float*)d_in[6];
    const float* W3  = (const float*)d_in[7];
    const float* b3  = (const float*)d_in[8];
    float* outp = (float*)d_out;

    const int prep_tasks = 749088 + 90112 + 16384 + 16384 + 2048;
    prep_kernel<<<(prep_tasks + 255) / 256, 256>>>(inp, W0, W1, W2, W3);

    cudaFuncSetAttribute(inr_hmma_kernel, cudaFuncAttributeMaxDynamicSharedMemorySize, SMEM_BYTES);
    inr_hmma_kernel<<<1568, TPB, SMEM_BYTES>>>(W0, b0, b1, b2, b3, outp);
}

// round 15
// speedup vs baseline: 1.6204x; 1.0051x over previous
#include <cuda_runtime.h>
#include <cuda_fp16.h>
#include <stdint.h>

#define TPB 128

// ---------------- smem layout (bytes) ----------------
// Branch-phase double-buffered A tiles (hi only): [32 rows][256B] = 8 KB each
#define T_BUF(b)   ((b) * 8192)
// Phase-A chunk buffers alias the same region: [32 rows][128B] = 4 KB each
#define PA_BUF(b)  ((b) * 4096)
#define OFF_SB0   16384
#define OFF_SB1   16896
#define OFF_SB2   17408
#define OFF_SP    17920
#define OFF_SQ    18432
#define OFF_SB3   18944    // 64 B
#define OFF_LUT   19008    // 648*4 = 2592
#define SMEM_BYTES 22528

// activation pre-scale (keeps branch-3 h1 within fp16 range)
#define ASCL   0.0625f
#define ASCL_I 16.0f

// ---------------- device images ----------------
// Zero-padded input: [8 ch][9 a1][9 a2][34 h][34 w]
__device__ __align__(16) float gInpP[749088];
// fp16 B-fragments packed as uint4 covering a PAIR of n-blocks:
//   entry = (kblk * npStride + npair) * 32 + lane,  lane = (n&7)*4 + ((k>>1)&3)
//   halves within entry: [( (n>>3)&1 )*4 + ((k>>3)&1)*2 + (k&1)]
__device__ __align__(16) __half gW0[90112];  // 704 x 128 (44 kblk x 8 npairs)
__device__ __align__(16) __half gW1[16384];  // 128 x 128 (8 x 8)
__device__ __align__(16) __half gW2[16384];
__device__ __align__(16) __half gW3[2048];   // 128 x 16 (8 x 1)

// ---------------- asm helpers ----------------
__device__ __forceinline__ uint32_t smem_u32(const void* p) {
    uint32_t a;
    asm("{ .reg .u64 t; cvta.to.shared.u64 t, %1; cvt.u32.u64 %0, t; }" : "=r"(a) : "l"(p));
    return a;
}
__device__ __forceinline__ void ldmx4(uint32_t r[4], uint32_t addr) {
    asm volatile("ldmatrix.sync.aligned.m8n8.x4.shared.b16 {%0,%1,%2,%3}, [%4];"
        : "=r"(r[0]), "=r"(r[1]), "=r"(r[2]), "=r"(r[3]) : "r"(addr));
}
__device__ __forceinline__ void mma16816(float* d, const uint32_t* a, uint32_t b0, uint32_t b1) {
    asm volatile("mma.sync.aligned.m16n8k16.row.col.f32.f16.f16.f32 "
        "{%0,%1,%2,%3}, {%4,%5,%6,%7}, {%8,%9}, {%0,%1,%2,%3};"
        : "+f"(d[0]), "+f"(d[1]), "+f"(d[2]), "+f"(d[3])
        : "r"(a[0]), "r"(a[1]), "r"(a[2]), "r"(a[3]), "r"(b0), "r"(b1));
}
__device__ __forceinline__ uint32_t packh2(float v0, float v1) {
    __half2 h = __floats2half2_rn(v0, v1);
    return *(uint32_t*)&h;
}
__device__ __forceinline__ float2 unpackh2(uint32_t u) {
    return __half22float2(*(__half2*)&u);
}

// GEMM: A (fp16) from swizzled smem via ldmatrix, B uint4 (n-pair) frags from global.
// Warp computes rows [0, 16*MT) x cols [npair0*16, (npair0+NT/2)*16). NT even.
template<int KS, int MT, int NT, int RLOG>
__device__ __forceinline__ void gemm_gb4(uint32_t aBuf,
    const uint4* __restrict__ gB,
    int kblk0, int npStride, int npair0, float* acc, int lane)
{
    const int rA = lane & 15;
    const int selA = lane >> 4;
    const uint32_t aRow = aBuf + (rA << RLOG);
    const int xorA = rA & 7;
    const uint4* b = gB + (kblk0 * npStride + npair0) * 32 + lane;
#pragma unroll
    for (int ks = 0; ks < KS; ks++) {
        const uint32_t offA = ((uint32_t)(((ks * 2 + selA) ^ xorA))) << 4;
        uint32_t ah[MT][4];
#pragma unroll
        for (int mt = 0; mt < MT; mt++)
            ldmx4(ah[mt], aRow + (mt << (RLOG + 4)) + offA);
        uint4 bv[NT / 2];
#pragma unroll
        for (int np = 0; np < NT / 2; np++) bv[np] = b[np * 32];
        b += npStride * 32;
#pragma unroll
        for (int np = 0; np < NT / 2; np++)
#pragma unroll
            for (int mt = 0; mt < MT; mt++) {
                mma16816(acc + (mt * NT + np * 2 + 0) * 4, ah[mt], bv[np].x, bv[np].y);
                mma16816(acc + (mt * NT + np * 2 + 1) * 4, ah[mt], bv[np].z, bv[np].w);
            }
    }
}

// epilogue: D frags (ASCL_I*acc + bias) -> relu -> fp16 (xASCL) -> smem hi tile
__device__ __forceinline__ void epi_acc(char* sm, uint32_t dstOff, const float* acc, const float* bias,
                                        int ng, int lane)
{
    const int rq = lane >> 2, nq = (lane & 3) * 2;
#pragma unroll
    for (int mt = 0; mt < 2; mt++) {
#pragma unroll
        for (int nt = 0; nt < 4; nt++) {
            int n = ng * 32 + nt * 8 + nq;
            float bb0 = bias[n], bb1 = bias[n + 1];
            const float* a = acc + (mt * 4 + nt) * 4;
#pragma unroll
            for (int half = 0; half < 2; half++) {
                int r = mt * 16 + rq + half * 8;
                float v0 = fmaxf(ASCL_I * a[half * 2 + 0] + bb0, 0.f) * ASCL;
                float v1 = fmaxf(ASCL_I * a[half * 2 + 1] + bb1, 0.f) * ASCL;
                int off = (r << 8) + ((((n >> 3) ^ (r & 7)) << 4)) + (n & 7) * 2;
                *(uint32_t*)(sm + dstOff + off) = packh2(v0, v1);
            }
        }
    }
}

// h1 epilogue from fp16-packed base registers
__device__ __forceinline__ void epi_base(char* sm, uint32_t dstOff, const uint32_t* baseH,
                                         const float* bias, float powv,
                                         const float* sP, const float* sQ,
                                         int ng, int lane, int hgrp)
{
    const int rq = lane >> 2, nq = (lane & 3) * 2;
#pragma unroll
    for (int mt = 0; mt < 2; mt++) {
#pragma unroll
        for (int nt = 0; nt < 4; nt++) {
            int n = ng * 32 + nt * 8 + nq;
            float e0 = fmaf(powv, sP[n], sQ[n]);
            float e1 = fmaf(powv, sP[n + 1], sQ[n + 1]);
            float bb0 = bias[n], bb1 = bias[n + 1];
#pragma unroll
            for (int half = 0; half < 2; half++) {
                int r = mt * 16 + rq + half * 8;
                float s = 1.f;
                if (hgrp == 0 && r < 4) s = (r < 2) ? 0.0625f : (2.f / 7.f);
                float2 bv = unpackh2(baseH[(mt * 4 + nt) * 2 + half]);
                float v0 = fmaxf(bv.x + bb0 + s * e0, 0.f) * ASCL;
                float v1 = fmaxf(bv.y + bb1 + s * e1, 0.f) * ASCL;
                int off = (r << 8) + ((((n >> 3) ^ (r & 7)) << 4)) + (n & 7) * 2;
                *(uint32_t*)(sm + dstOff + off) = packh2(v0, v1);
            }
        }
    }
}

// ---------------- prep kernel: padded input + fp16 B-frag (n-pair uint4) weights ----------------
__device__ __forceinline__ void pack_frag(__half* dst, float v, int k, int n, int npStride) {
    int entry = ((k >> 4) * npStride + (n >> 4)) * 32 + (n & 7) * 4 + ((k >> 1) & 3);
    int sub = ((n >> 3) & 1) * 4 + ((k >> 3) & 1) * 2 + (k & 1);
    dst[entry * 8 + sub] = __float2half_rn(v);
}

__global__ void prep_kernel(const float* __restrict__ inp,
                            const float* __restrict__ W0, const float* __restrict__ W1,
                            const float* __restrict__ W2, const float* __restrict__ W3) {
    int idx = blockIdx.x * 256 + threadIdx.x;
    const int nP = 749088, n0 = 90112, n1 = 16384, n2 = 16384, n3 = 2048;
    if (idx < nP) {
        int w1 = idx % 34, h1 = (idx / 34) % 34;
        int a2 = (idx / 1156) % 9, a1 = (idx / 10404) % 9, ch = idx / 93636;
        bool ok = (a1 >= 1 && a1 <= 7 && a2 >= 1 && a2 <= 7 &&
                   h1 >= 1 && h1 <= 32 && w1 >= 1 && w1 <= 32);
        gInpP[idx] = ok ? inp[ch * 50176 + (a1 - 1) * 7168 + (a2 - 1) * 1024
                              + (h1 - 1) * 32 + (w1 - 1)] : 0.f;
    } else if (idx < nP + n0) {
        int r = idx - nP, k = r >> 7, n = r & 127;
        float v = (k < 648) ? W0[k * 128 + n] : 0.f;
        pack_frag(gW0, v, k, n, 8);
    } else if (idx < nP + n0 + n1) {
        int r = idx - nP - n0, k = r >> 7, n = r & 127;
        pack_frag(gW1, W1[k * 128 + n], k, n, 8);
    } else if (idx < nP + n0 + n1 + n2) {
        int r = idx - nP - n0 - n1, k = r >> 7, n = r & 127;
        pack_frag(gW2, W2[k * 128 + n], k, n, 8);
    } else if (idx < nP + n0 + n1 + n2 + n3) {
        int r = idx - nP - n0 - n1 - n2, k = r >> 4, n = r & 15;
        float v = (n < 12) ? W3[k * 12 + n] : 0.f;
        pack_frag(gW3, v, k, n, 1);
    }
}

// ---------------- main kernel ----------------
__global__ __launch_bounds__(TPB, 4)
void inr_hmma_kernel(const float* __restrict__ W0,
                     const float* __restrict__ b0g, const float* __restrict__ b1g,
                     const float* __restrict__ b2g, const float* __restrict__ b3g,
                     float* __restrict__ outp) {
    extern __shared__ char sm[];
    const uint32_t sbase = smem_u32(sm);
    const int tid = threadIdx.x;
    const int lane = tid & 31, w = tid >> 5;
    const int ng = w;                          // 4 warps: 1 m-group (32 rows) x 4 n-groups

    const int blk = blockIdx.x;
    const int ablk = blk >> 5, hgrp = blk & 31;   // 32 positions = 1 h-row x 32 w
    const int ahi = ablk / 7, awi = ablk % 7;

    float* sb0 = (float*)(sm + OFF_SB0);
    float* sb1 = (float*)(sm + OFF_SB1);
    float* sb2 = (float*)(sm + OFF_SB2);
    float* sP  = (float*)(sm + OFF_SP);
    float* sQ  = (float*)(sm + OFF_SQ);
    float* sb3 = (float*)(sm + OFF_SB3);
    int*   lut = (int*)(sm + OFF_LUT);

    for (int c = tid; c < 128; c += TPB) {
        sb0[c] = b0g[c]; sb1[c] = b1g[c]; sb2[c] = b2g[c];
        sP[c] = W0[716 * 128 + c] + W0[717 * 128 + c];
        sQ[c] = W0[718 * 128 + c] + W0[719 * 128 + c];
    }
    if (tid < 12) sb3[tid] = b3g[tid];
    for (int k = tid; k < 648; k += TPB) {
        int aj = k % 3, ai = (k / 3) % 3, kj = (k / 9) % 3, ki = (k / 27) % 3, ch = k / 81;
        lut[k] = ch * 93636 + ai * 10404 + aj * 1156 + ki * 34 + kj;
    }
    __syncthreads();

    const uint4* gw0 = (const uint4*)gW0;
    const uint4* gw1 = (const uint4*)gW1;
    const uint4* gw2 = (const uint4*)gW2;
    const uint4* gw3 = (const uint4*)gW3;

    // ================= Phase A: base = q_feat @ W0 (11 chunks of K=64, ping-pong) ======
    float base_[32];
#pragma unroll
    for (int i = 0; i < 32; i++) base_[i] = 0.f;

    const int gm = tid & 31;          // row (position = w-index)
    const int gstrip = tid >> 5;      // k-pair strip (0..3)
    const int ibase = ahi * 10404 + awi * 1156 + hgrp * 34 + gm;

    auto gather = [&](int c, bool check) {
        char* dh = sm + PA_BUF(c & 1);
#pragma unroll
        for (int q = 0; q < 8; q++) {
            int kp = gstrip * 8 + q;
            int kk = c * 64 + kp * 2;
            float v0, v1;
            if (!check) {
                v0 = gInpP[ibase + lut[kk]];
                v1 = gInpP[ibase + lut[kk + 1]];
            } else {
                v0 = (kk < 648) ? gInpP[ibase + lut[kk]] : 0.f;
                v1 = (kk + 1 < 648) ? gInpP[ibase + lut[kk + 1]] : 0.f;
            }
            int off = gm * 128 + ((((kp >> 2) ^ (gm & 7)) << 4)) + (kp & 3) * 4;
            *(uint32_t*)(dh + off) = packh2(v0, v1);
        }
    };

    gather(0, false);
    __syncthreads();
    for (int c = 0; c < 11; c++) {
        if (c < 10) gather(c + 1, c + 1 == 10);
        gemm_gb4<4, 2, 4, 7>(sbase + PA_BUF(c & 1), gw0,
                             c * 4, 8, ng * 2, base_, lane);
        __syncthreads();
    }

    // pack base into fp16 registers (frees 16 regs for load pipelining in branch phase)
    uint32_t baseH[16];
#pragma unroll
    for (int t = 0; t < 8; t++) {
        baseH[t * 2 + 0] = packh2(base_[t * 4 + 0], base_[t * 4 + 1]);
        baseH[t * 2 + 1] = packh2(base_[t * 4 + 2], base_[t * 4 + 3]);
    }

    // ================= 4 branches (ping-pong hi-only activation tiles) =================
    float y[8];
#pragma unroll
    for (int i = 0; i < 8; i++) y[i] = 0.f;
    float powv = 32.f;
    int p = 0;

    for (int br = 0; br < 4; br++) {
        // h1 = relu(base + b0 + s*(powv*P + Q)) -> buf p
        epi_base(sm, T_BUF(p), baseH, sb0, powv, sP, sQ, ng, lane, hgrp);
        __syncthreads();

        float acc[32];
#pragma unroll
        for (int i = 0; i < 32; i++) acc[i] = 0.f;
        gemm_gb4<8, 2, 4, 8>(sbase + T_BUF(p), gw1, 0, 8, ng * 2, acc, lane);
        // h2 -> buf p^1 (writes other buffer; no pre-sync needed)
        epi_acc(sm, T_BUF(p ^ 1), acc, sb1, ng, lane);
        __syncthreads();

#pragma unroll
        for (int i = 0; i < 32; i++) acc[i] = 0.f;
        gemm_gb4<8, 2, 4, 8>(sbase + T_BUF(p ^ 1), gw2, 0, 8, ng * 2, acc, lane);
        // h3 -> buf p
        epi_acc(sm, T_BUF(p), acc, sb2, ng, lane);
        __syncthreads();

        // y += (h3/16) @ W3: warps ng<2, each uses its half of the n-pair uint4
        if (ng < 2) {
            const int rA = lane & 15;
            const int selA = lane >> 4;
            const uint32_t aRow = sbase + T_BUF(p) + (rA << 8);
            const int xorA = rA & 7;
#pragma unroll
            for (int ks = 0; ks < 8; ks++) {
                const uint32_t offA = ((uint32_t)(((ks * 2 + selA) ^ xorA))) << 4;
                uint32_t ah[2][4];
                ldmx4(ah[0], aRow + offA);
                ldmx4(ah[1], aRow + 4096 + offA);
                uint4 bv = gw3[ks * 32 + lane];
                uint32_t b0 = ng ? bv.z : bv.x;
                uint32_t b1 = ng ? bv.w : bv.y;
                mma16816(y + 0, ah[0], b0, b1);
                mma16816(y + 4, ah[1], b0, b1);
            }
        }
        p ^= 1;
        powv *= 32.f;
    }

    // ---- scatter (pixel shuffle); y_true = 16*y, out = 0.25*sum + b3 = 4*y + b3 ----
    if (ng < 2) {
        const int rq = lane >> 2, nq = (lane & 3) * 2;
#pragma unroll
        for (int mt = 0; mt < 2; mt++)
#pragma unroll
            for (int half = 0; half < 2; half++)
#pragma unroll
                for (int j = 0; j < 2; j++) {
                    int n = ng * 8 + nq + j;
                    if (n < 12) {
                        int r = mt * 16 + rq + half * 8;   // position (w-index) 0..31
                        float val = 4.0f * y[mt * 4 + half * 2 + j] + sb3[n];
                        int rgb = n >> 2, pr = (n >> 1) & 1, qc = n & 1;
                        outp[rgb * 200704 + ahi * 28672 + awi * 4096 +
                             (2 * hgrp + pr) * 64 + (2 * r + qc)] = val;
                    }
                }
    }
}

extern "C" void kernel_launch(void* const* d_in, const int* in_sizes, int n_in,
                              void* d_out, int out_size) {
    (void)in_sizes; (void)n_in; (void)out_size;
    const float* inp = (const float*)d_in[0];
    const float* W0  = (const float*)d_in[1];
    const float* b0  = (const float*)d_in[2];
    const float* W1  = (const float*)d_in[3];
    const float* b1  = (const float*)d_in[4];
    const float* W2  = (const float*)d_in[5];
    const float* b2  = (const float*)d_in[6];
    const float* W3  = (const float*)d_in[7];
    const float* b3  = (const float*)d_in[8];
    float* outp = (float*)d_out;

    const int prep_tasks = 749088 + 90112 + 16384 + 16384 + 2048;
    prep_kernel<<<(prep_tasks + 255) / 256, 256>>>(inp, W0, W1, W2, W3);

    cudaFuncSetAttribute(inr_hmma_kernel, cudaFuncAttributeMaxDynamicSharedMemorySize, SMEM_BYTES);
    inr_hmma_kernel<<<1568, TPB, SMEM_BYTES>>>(W0, b0, b1, b2, b3, outp);
}